// round 9
// baseline (speedup 1.0000x reference)
#include <cuda_runtime.h>
#include <cuda_bf16.h>
#include <cstdint>

#define MARGIN 0.5f
#define POS_W 1.0f
#define NEG_W 1.0f

#define BLOCKS_PER_BATCH 4
#define R_THREADS 256
#define MAX_PARTIALS 8192
#define MAX_B 1024

// Scratch (allocations forbidden; __device__ globals).
// Every g_partial slot used is rewritten each call -> no zeroing needed.
__device__ float g_partial[MAX_PARTIALS];
__device__ unsigned int g_arrival = 0;   // last block resets to 0 each call

// Streaming load with 256B L2 prefetch hint: DRAM sees 256B-granular requests.
__device__ __forceinline__ float4 ldg_stream_256(const float4* p) {
    float4 v;
    asm volatile("ld.global.nc.L2::256B.v4.f32 {%0,%1,%2,%3}, [%4];"
                 : "=f"(v.x), "=f"(v.y), "=f"(v.z), "=f"(v.w) : "l"(p));
    return v;
}

__global__ __launch_bounds__(R_THREADS, 8) void fused_loss_kernel(
    const float* __restrict__ graph,
    const int* __restrict__ labels,
    float* __restrict__ out,
    int B, int ne_per_batch) {

    const int b = blockIdx.x / BLOCKS_PER_BATCH;
    const int chunk = blockIdx.x % BLOCKS_PER_BATCH;
    const int vec_per_batch = ne_per_batch >> 2;               // float4 count
    const int vec_per_chunk = vec_per_batch / BLOCKS_PER_BATCH;

    const float4* __restrict__ base =
        reinterpret_cast<const float4*>(graph) +
        (size_t)b * vec_per_batch + (size_t)chunk * vec_per_chunk;

    // 4 independent accumulators, unroll-4, 256B-granular streaming loads.
    float a0 = 0.0f, a1 = 0.0f, a2 = 0.0f, a3 = 0.0f;
    int i = threadIdx.x;
    const int stride = R_THREADS;
    const int n4 = vec_per_chunk & ~(4 * stride - 1);  // full unroll-4 span
    for (; i < n4; i += 4 * stride) {
        float4 v0 = ldg_stream_256(&base[i]);
        float4 v1 = ldg_stream_256(&base[i + stride]);
        float4 v2 = ldg_stream_256(&base[i + 2 * stride]);
        float4 v3 = ldg_stream_256(&base[i + 3 * stride]);
        a0 += (v0.x + v0.y) + (v0.z + v0.w);
        a1 += (v1.x + v1.y) + (v1.z + v1.w);
        a2 += (v2.x + v2.y) + (v2.z + v2.w);
        a3 += (v3.x + v3.y) + (v3.z + v3.w);
    }
    for (; i < vec_per_chunk; i += stride) {
        float4 v = ldg_stream_256(&base[i]);
        a0 += (v.x + v.y) + (v.z + v.w);
    }
    float acc = (a0 + a1) + (a2 + a3);

    // block reduce
    #pragma unroll
    for (int off = 16; off > 0; off >>= 1)
        acc += __shfl_xor_sync(0xFFFFFFFFu, acc, off);

    __shared__ float warp_sums[R_THREADS / 32];
    const int lane = threadIdx.x & 31, wid = threadIdx.x >> 5;
    if (lane == 0) warp_sums[wid] = acc;
    __syncthreads();

    __shared__ bool is_last;
    if (wid == 0) {
        float s = (lane < R_THREADS / 32) ? warp_sums[lane] : 0.0f;
        #pragma unroll
        for (int off = 4; off > 0; off >>= 1)
            s += __shfl_xor_sync(0xFFFFFFFFu, s, off);
        if (lane == 0) {
            g_partial[blockIdx.x] = s;
            __threadfence();
            unsigned int prev = atomicAdd(&g_arrival, 1u);
            is_last = (prev == gridDim.x - 1);
        }
    }
    __syncthreads();

    if (!is_last) return;

    // ---- tail: last block computes pooled sims + pair loss ----
    if (threadIdx.x == 0) g_arrival = 0;   // reset for next graph replay

    __shared__ float gs[MAX_B];
    __shared__ int lab[MAX_B];
    const float inv_ne = 1.0f / (float)ne_per_batch;

    for (int t = threadIdx.x; t < B; t += R_THREADS) {
        float s = 0.0f;
        #pragma unroll
        for (int c = 0; c < BLOCKS_PER_BATCH; ++c)
            s += g_partial[t * BLOCKS_PER_BATCH + c];
        gs[t] = s * inv_ne;
        lab[t] = labels[t];
    }
    __syncthreads();

    // Balanced pair partition: thread t handles linearized pairs [k0, k1).
    // cum(i) = i*(2B - i - 1)/2 = number of pairs in rows < i.
    const int P = B * (B - 1) / 2;
    const int tid = threadIdx.x;
    const int k0 = (int)(((long long)P * tid) / R_THREADS);
    const int k1 = (int)(((long long)P * (tid + 1)) / R_THREADS);

    float pacc = 0.0f;
    if (k1 > k0) {
        const float fB = 2.0f * (float)B - 1.0f;
        int ri = (int)((fB - sqrtf(fB * fB - 8.0f * (float)k0)) * 0.5f);
        if (ri < 0) ri = 0;
        if (ri > B - 2) ri = B - 2;
        while ((long long)ri * (2 * B - ri - 1) / 2 > (long long)k0) --ri;
        while ((long long)(ri + 1) * (2 * B - ri - 2) / 2 <= (long long)k0) ++ri;
        int j = ri + 1 + (k0 - (int)((long long)ri * (2 * B - ri - 1) / 2));

        float gi = gs[ri];
        int li = lab[ri];
        for (int k = k0; k < k1; ++k) {
            const float sim = gi * gs[j];
            const float pos = fmaxf(MARGIN - sim, 0.0f);
            const float neg = fmaxf(sim - (1.0f - MARGIN), 0.0f);
            pacc += (li == lab[j]) ? (POS_W * pos) : (NEG_W * neg);
            if (++j == B) { ++ri; j = ri + 1; gi = gs[ri]; li = lab[ri]; }
        }
    }

    #pragma unroll
    for (int off = 16; off > 0; off >>= 1)
        pacc += __shfl_xor_sync(0xFFFFFFFFu, pacc, off);

    __shared__ float pw[R_THREADS / 32];
    if (lane == 0) pw[wid] = pacc;
    __syncthreads();

    if (wid == 0) {
        float s = (lane < R_THREADS / 32) ? pw[lane] : 0.0f;
        #pragma unroll
        for (int off = 4; off > 0; off >>= 1)
            s += __shfl_xor_sync(0xFFFFFFFFu, s, off);
        if (lane == 0) {
            const float num_pairs = 0.5f * (float)B * (float)(B - 1);
            out[0] = s / num_pairs;
        }
    }
}

extern "C" void kernel_launch(void* const* d_in, const int* in_sizes, int n_in,
                              void* d_out, int out_size) {
    const float* graph = (const float*)d_in[0];
    const int* labels = (const int*)d_in[1];
    float* out = (float*)d_out;

    const int total = in_sizes[0];   // B * N * N
    const int B = in_sizes[1];       // 256
    const int ne = total / B;        // N*N = 262144

    fused_loss_kernel<<<B * BLOCKS_PER_BATCH, R_THREADS>>>(graph, labels, out, B, ne);
}

// round 10
// speedup vs baseline: 1.0137x; 1.0137x over previous
#include <cuda_runtime.h>
#include <cuda_bf16.h>
#include <cstdint>

#define MARGIN 0.5f
#define POS_W 1.0f
#define NEG_W 1.0f

#define BLOCKS_PER_BATCH 4
#define R_THREADS 256
#define MAX_PARTIALS 8192
#define MAX_B 1024

// Scratch (allocations forbidden; __device__ globals).
// Every g_partial slot used is rewritten each call -> no zeroing needed.
__device__ float g_partial[MAX_PARTIALS];
__device__ unsigned int g_arrival = 0;   // last block resets to 0 each call

// 256-bit global load (sm_100+): one LDG.E.256 per 8 floats.
// Warp footprint: 32 lanes x 32B = 1024B contiguous per instruction.
__device__ __forceinline__ void ldg256(const float* p, float v[8]) {
    asm volatile("ld.global.nc.v8.f32 {%0,%1,%2,%3,%4,%5,%6,%7}, [%8];"
                 : "=f"(v[0]), "=f"(v[1]), "=f"(v[2]), "=f"(v[3]),
                   "=f"(v[4]), "=f"(v[5]), "=f"(v[6]), "=f"(v[7])
                 : "l"(p));
}

__global__ __launch_bounds__(R_THREADS, 8) void fused_loss_kernel(
    const float* __restrict__ graph,
    const int* __restrict__ labels,
    float* __restrict__ out,
    int B, int ne_per_batch) {

    const int b = blockIdx.x / BLOCKS_PER_BATCH;
    const int chunk = blockIdx.x % BLOCKS_PER_BATCH;
    const int f_per_batch = ne_per_batch;                       // floats
    const int f_per_chunk = f_per_batch / BLOCKS_PER_BATCH;     // 65536 floats

    const float* __restrict__ base =
        graph + (size_t)b * f_per_batch + (size_t)chunk * f_per_chunk;

    // Each thread: 8 v8-loads per 2-deep unrolled step; 2 independent accs.
    // Per iteration the warp fetches 2 x 1024B contiguous spans.
    float a0 = 0.0f, a1 = 0.0f;
    const int stride8 = R_THREADS * 8;                 // floats per block-step
    const int nsteps = f_per_chunk / (2 * stride8);    // 65536/4096 = 16
    const float* p = base + threadIdx.x * 8;
    for (int s = 0; s < nsteps; ++s) {
        float v0[8], v1[8];
        ldg256(p, v0);
        ldg256(p + stride8, v1);
        p += 2 * stride8;
        a0 += ((v0[0] + v0[1]) + (v0[2] + v0[3])) +
              ((v0[4] + v0[5]) + (v0[6] + v0[7]));
        a1 += ((v1[0] + v1[1]) + (v1[2] + v1[3])) +
              ((v1[4] + v1[5]) + (v1[6] + v1[7]));
    }
    float acc = a0 + a1;

    // block reduce
    #pragma unroll
    for (int off = 16; off > 0; off >>= 1)
        acc += __shfl_xor_sync(0xFFFFFFFFu, acc, off);

    __shared__ float warp_sums[R_THREADS / 32];
    const int lane = threadIdx.x & 31, wid = threadIdx.x >> 5;
    if (lane == 0) warp_sums[wid] = acc;
    __syncthreads();

    __shared__ bool is_last;
    if (wid == 0) {
        float s = (lane < R_THREADS / 32) ? warp_sums[lane] : 0.0f;
        #pragma unroll
        for (int off = 4; off > 0; off >>= 1)
            s += __shfl_xor_sync(0xFFFFFFFFu, s, off);
        if (lane == 0) {
            g_partial[blockIdx.x] = s;
            __threadfence();
            unsigned int prev = atomicAdd(&g_arrival, 1u);
            is_last = (prev == gridDim.x - 1);
        }
    }
    __syncthreads();

    if (!is_last) return;

    // ---- tail: last block computes pooled sims + pair loss ----
    if (threadIdx.x == 0) g_arrival = 0;   // reset for next graph replay

    __shared__ float gs[MAX_B];
    __shared__ int lab[MAX_B];
    const float inv_ne = 1.0f / (float)ne_per_batch;

    for (int t = threadIdx.x; t < B; t += R_THREADS) {
        float s = 0.0f;
        #pragma unroll
        for (int c = 0; c < BLOCKS_PER_BATCH; ++c)
            s += g_partial[t * BLOCKS_PER_BATCH + c];
        gs[t] = s * inv_ne;
        lab[t] = labels[t];
    }
    __syncthreads();

    // Balanced pair partition: thread t handles linearized pairs [k0, k1).
    const int P = B * (B - 1) / 2;
    const int tid = threadIdx.x;
    const int k0 = (int)(((long long)P * tid) / R_THREADS);
    const int k1 = (int)(((long long)P * (tid + 1)) / R_THREADS);

    float pacc = 0.0f;
    if (k1 > k0) {
        const float fB = 2.0f * (float)B - 1.0f;
        int ri = (int)((fB - sqrtf(fB * fB - 8.0f * (float)k0)) * 0.5f);
        if (ri < 0) ri = 0;
        if (ri > B - 2) ri = B - 2;
        while ((long long)ri * (2 * B - ri - 1) / 2 > (long long)k0) --ri;
        while ((long long)(ri + 1) * (2 * B - ri - 2) / 2 <= (long long)k0) ++ri;
        int j = ri + 1 + (k0 - (int)((long long)ri * (2 * B - ri - 1) / 2));

        float gi = gs[ri];
        int li = lab[ri];
        for (int k = k0; k < k1; ++k) {
            const float sim = gi * gs[j];
            const float pos = fmaxf(MARGIN - sim, 0.0f);
            const float neg = fmaxf(sim - (1.0f - MARGIN), 0.0f);
            pacc += (li == lab[j]) ? (POS_W * pos) : (NEG_W * neg);
            if (++j == B) { ++ri; j = ri + 1; gi = gs[ri]; li = lab[ri]; }
        }
    }

    #pragma unroll
    for (int off = 16; off > 0; off >>= 1)
        pacc += __shfl_xor_sync(0xFFFFFFFFu, pacc, off);

    __shared__ float pw[R_THREADS / 32];
    if (lane == 0) pw[wid] = pacc;
    __syncthreads();

    if (wid == 0) {
        float s = (lane < R_THREADS / 32) ? pw[lane] : 0.0f;
        #pragma unroll
        for (int off = 4; off > 0; off >>= 1)
            s += __shfl_xor_sync(0xFFFFFFFFu, s, off);
        if (lane == 0) {
            const float num_pairs = 0.5f * (float)B * (float)(B - 1);
            out[0] = s / num_pairs;
        }
    }
}

extern "C" void kernel_launch(void* const* d_in, const int* in_sizes, int n_in,
                              void* d_out, int out_size) {
    const float* graph = (const float*)d_in[0];
    const int* labels = (const int*)d_in[1];
    float* out = (float*)d_out;

    const int total = in_sizes[0];   // B * N * N
    const int B = in_sizes[1];       // 256
    const int ne = total / B;        // N*N = 262144

    fused_loss_kernel<<<B * BLOCKS_PER_BATCH, R_THREADS>>>(graph, labels, out, B, ne);
}